// round 12
// baseline (speedup 1.0000x reference)
#include <cuda_runtime.h>
#include <cuda_bf16.h>
#include <cuda_fp16.h>
#include <cstdint>

// Problem constants (B=1 fixed)
#define S_LEN   2048
#define HID     6144
#define QKV_OUT 6400   // HID + 2*128
#define NH      48
#define HD      128
#define KDIM    6144   // GEMM K (both projections)

// Scratch (no cudaMalloc allowed)
__device__ float    g_qkv [S_LEN * QKV_OUT];
__device__ float    g_attn[S_LEN * HID];
__device__ __half   g_wh  [QKV_OUT * HID];   // wqkv fp16
__device__ __half   g_woh [HID * HID];       // wo fp16
__device__ __half   g_ah  [S_LEN * HID];     // activation fp16
__device__ uint32_t g_kp  [S_LEN * 128];     // K bf16 hi|lo planes (packed pairs)
__device__ uint32_t g_vp  [S_LEN * 128];     // V bf16 hi|lo planes

// ---------------------------------------------------------------------------
// helpers
// ---------------------------------------------------------------------------
__device__ __forceinline__ uint32_t smem_u32(const void* p) {
    uint32_t a;
    asm("{ .reg .u64 t; cvta.to.shared.u64 t, %1; cvt.u32.u64 %0, t; }"
        : "=r"(a) : "l"(p));
    return a;
}

__device__ __forceinline__ void cp16(uint32_t dst, const void* src) {
    asm volatile("cp.async.cg.shared.global [%0], [%1], 16;"
                 :: "r"(dst), "l"(src) : "memory");
}
#define CP_COMMIT() asm volatile("cp.async.commit_group;" ::: "memory")
#define CP_WAIT0()  asm volatile("cp.async.wait_group 0;" ::: "memory")
#define CP_WAIT2()  asm volatile("cp.async.wait_group 2;" ::: "memory")

__device__ __forceinline__ void mma_bf16(float* d, const uint32_t* a, const uint32_t* b) {
    asm volatile(
        "mma.sync.aligned.m16n8k16.row.col.f32.bf16.bf16.f32 "
        "{%0,%1,%2,%3}, {%4,%5,%6,%7}, {%8,%9}, {%0,%1,%2,%3};"
        : "+f"(d[0]), "+f"(d[1]), "+f"(d[2]), "+f"(d[3])
        : "r"(a[0]), "r"(a[1]), "r"(a[2]), "r"(a[3]), "r"(b[0]), "r"(b[1]));
}
__device__ __forceinline__ void mma_f16(float* d, const uint32_t* a, const uint32_t* b) {
    asm volatile(
        "mma.sync.aligned.m16n8k16.row.col.f32.f16.f16.f32 "
        "{%0,%1,%2,%3}, {%4,%5,%6,%7}, {%8,%9}, {%0,%1,%2,%3};"
        : "+f"(d[0]), "+f"(d[1]), "+f"(d[2]), "+f"(d[3])
        : "r"(a[0]), "r"(a[1]), "r"(a[2]), "r"(a[3]), "r"(b[0]), "r"(b[1]));
}

__device__ __forceinline__ void ldsm_x4(uint32_t* r, uint32_t addr) {
    asm volatile("ldmatrix.sync.aligned.m8n8.x4.shared.b16 {%0,%1,%2,%3}, [%4];"
                 : "=r"(r[0]), "=r"(r[1]), "=r"(r[2]), "=r"(r[3]) : "r"(addr));
}
__device__ __forceinline__ void ldsm_x2(uint32_t* r, uint32_t addr) {
    asm volatile("ldmatrix.sync.aligned.m8n8.x2.shared.b16 {%0,%1}, [%2];"
                 : "=r"(r[0]), "=r"(r[1]) : "r"(addr));
}
__device__ __forceinline__ void ldsm_x2_t(uint32_t& r0, uint32_t& r1, uint32_t addr) {
    asm volatile("ldmatrix.sync.aligned.m8n8.x2.trans.shared.b16 {%0,%1}, [%2];"
                 : "=r"(r0), "=r"(r1) : "r"(addr));
}

// ---- bf16 split helpers (attention) ----
__device__ __forceinline__ void pack_split2(float x, float y, uint32_t& hi, uint32_t& lo) {
    __nv_bfloat162 h = __floats2bfloat162_rn(x, y);
    float2 hf = __bfloat1622float2(h);
    __nv_bfloat162 l = __floats2bfloat162_rn(x - hf.x, y - hf.y);
    hi = *reinterpret_cast<uint32_t*>(&h);
    lo = *reinterpret_cast<uint32_t*>(&l);
}
__device__ __forceinline__ void split16(const float* src, uint32_t* hi, uint32_t* lo,
                                        float scale) {
    #pragma unroll
    for (int i = 0; i < 4; i++) {
        float4 f = *(const float4*)(src + i * 4);
        f.x *= scale; f.y *= scale; f.z *= scale; f.w *= scale;
        uint32_t h0, l0, h1, l1;
        pack_split2(f.x, f.y, h0, l0);
        pack_split2(f.z, f.w, h1, l1);
        hi[i * 2] = h0; hi[i * 2 + 1] = h1;
        lo[i * 2] = l0; lo[i * 2 + 1] = l1;
    }
}

// ---------------------------------------------------------------------------
// conversion / prepack kernels (run once per launch)
// ---------------------------------------------------------------------------
__global__ void __launch_bounds__(256) f32_to_f16_k(const float* __restrict__ in,
                                                    __half* __restrict__ out, int n4) {
    const int i = blockIdx.x * 256 + threadIdx.x;
    if (i < n4) {
        float4 f = ((const float4*)in)[i];
        __half2 a = __floats2half2_rn(f.x, f.y);
        __half2 b = __floats2half2_rn(f.z, f.w);
        ((uint2*)out)[i] = make_uint2(*reinterpret_cast<uint32_t*>(&a),
                                      *reinterpret_cast<uint32_t*>(&b));
    }
}

// split K/V rows of qkv into bf16 hi/lo planes: row r -> kp[r*128 + 0..63]=hi,
// +64..127 = lo (u32 pairs), same for V.
__global__ void __launch_bounds__(256) kv_prepack_k(const float* __restrict__ qkv,
                                                    uint32_t* __restrict__ kp,
                                                    uint32_t* __restrict__ vp) {
    const int i = blockIdx.x * 256 + threadIdx.x;   // 0 .. 2048*8-1
    if (i < S_LEN * 8) {
        const int r = i >> 3, c16 = (i & 7) * 16;
        const float* src = qkv + (long)r * QKV_OUT + HID;
        split16(src + c16,      kp + r * 128 + (c16 >> 1), kp + r * 128 + (c16 >> 1) + 64, 1.0f);
        split16(src + HD + c16, vp + r * 128 + (c16 >> 1), vp + r * 128 + (c16 >> 1) + 64, 1.0f);
    }
}

// ---------------------------------------------------------------------------
// fp16 async GEMM: C[M,N] = Ah[M,K] * Bh[N,K]^T + bias[N]  (K=6144)
// CTA 128x128, BK=32, 256 threads, warp tile 64x32, 4-stage cp.async ring.
// Tile pitch 80B. 2 CTAs/SM.
// ---------------------------------------------------------------------------
#define TILE_B 10240                // 128 rows * 80B
#define STG_B  (2 * TILE_B)         // A + B per stage (20480B)
#define NSTG   (KDIM / 32)          // 192

__global__ void __launch_bounds__(256, 2) gemm_f16a(
    const __half* __restrict__ Ah, const __half* __restrict__ Bh,
    const float* __restrict__ bias, float* __restrict__ C, int N)
{
    extern __shared__ char gsm[];
    const uint32_t smb = smem_u32(gsm);

    const int tid = threadIdx.x;
    const int wid = tid >> 5, lid = tid & 31;
    const int g   = lid >> 2;
    const int t4  = lid & 3;
    const int wr  = wid >> 2;
    const int wc  = wid & 3;

    const int bm = blockIdx.y * 128, bn = blockIdx.x * 128;

    const int lrow = tid >> 1;
    const int lel  = (tid & 1) * 16;
    const __half* Ag = Ah + (long)(bm + lrow) * KDIM + lel;
    const __half* Bg = Bh + (long)(bn + lrow) * KDIM + lel;
    const uint32_t sdst = smb + (uint32_t)(lrow * 80 + lel * 2);

    const uint32_t a_row = (uint32_t)((wr * 64 + (lid & 15)) * 80 + (lid >> 4) * 16);
    const uint32_t b_row = (uint32_t)((wc * 32 + (lid & 7)) * 80 + ((lid >> 3) & 1) * 16);

    float acc[4][4][4];
    #pragma unroll
    for (int i = 0; i < 4; i++)
        #pragma unroll
        for (int j = 0; j < 4; j++)
            #pragma unroll
            for (int k = 0; k < 4; k++) acc[i][j][k] = 0.0f;

    // prologue: issue stages 0..2
    #pragma unroll
    for (int s = 0; s < 3; s++) {
        const uint32_t sb = sdst + s * STG_B;
        const long go = (long)s * 32;
        cp16(sb,          Ag + go);  cp16(sb + 16,          Ag + go + 8);
        cp16(sb + TILE_B, Bg + go);  cp16(sb + TILE_B + 16, Bg + go + 8);
        CP_COMMIT();
    }

    int slot = 0;
    for (int s = 0; s < NSTG; s++) {
        CP_WAIT2();
        __syncthreads();

        if (s + 3 < NSTG) {
            const int wslot = (slot + 3) & 3;
            const uint32_t sb = sdst + wslot * STG_B;
            const long go = (long)(s + 3) * 32;
            cp16(sb,          Ag + go);  cp16(sb + 16,          Ag + go + 8);
            cp16(sb + TILE_B, Bg + go);  cp16(sb + TILE_B + 16, Bg + go + 8);
        }
        CP_COMMIT();

        const uint32_t abase = smb + slot * STG_B + a_row;
        const uint32_t bbase = smb + slot * STG_B + TILE_B + b_row;

        #pragma unroll
        for (int ks = 0; ks < 2; ks++) {
            uint32_t ah[4][4];
            #pragma unroll
            for (int mt = 0; mt < 4; mt++)
                ldsm_x4(ah[mt], abase + ks * 32 + mt * (16 * 80));
            #pragma unroll
            for (int nt = 0; nt < 4; nt++) {
                uint32_t bh[2];
                ldsm_x2(bh, bbase + ks * 32 + nt * (8 * 80));
                #pragma unroll
                for (int mt = 0; mt < 4; mt++) mma_f16(acc[mt][nt], ah[mt], bh);
            }
        }

        slot = (slot + 1) & 3;
    }

    // epilogue
    #pragma unroll
    for (int mt = 0; mt < 4; mt++) {
        const int row = bm + wr * 64 + mt * 16 + g;
        #pragma unroll
        for (int nt = 0; nt < 4; nt++) {
            const int col = bn + wc * 32 + nt * 8 + t4 * 2;
            const float b0 = bias[col], b1 = bias[col + 1];
            float2 lo, hi;
            lo.x = acc[mt][nt][0] + b0; lo.y = acc[mt][nt][1] + b1;
            hi.x = acc[mt][nt][2] + b0; hi.y = acc[mt][nt][3] + b1;
            *(float2*)&C[(long)row * N + col]       = lo;
            *(float2*)&C[(long)(row + 8) * N + col] = hi;
        }
    }
}

// ---------------------------------------------------------------------------
// MQA causal flash attention, bf16-split HMMA, prepacked K/V + cp.async
// double buffer. CTA: 128 threads, BQ=64, BKV=64, D=128.
// smem: Q tile [64][132] + 2 slots x (K,V) tiles [64][132] each.
// ---------------------------------------------------------------------------
#define QP 132
#define KVSLOT (64 * QP)            // u32 per tile

__global__ void __launch_bounds__(128) mqa_flash_hmma(
    const float* __restrict__ qkv,
    const uint32_t* __restrict__ kp, const uint32_t* __restrict__ vp,
    float* __restrict__ attn_out)
{
    extern __shared__ uint32_t asm_[];
    uint32_t* q_s = asm_;                       // [64][QP]
    const uint32_t smb = smem_u32(asm_);

    const int h  = blockIdx.y;
    const int bq = blockIdx.x;
    const int q0 = bq * 64;
    const int tid = threadIdx.x;
    const int wid = tid >> 5, lid = tid & 31;
    const int g = lid >> 2, t4 = lid & 3;

    const int lr   = tid >> 1;                  // row 0..63
    const int half = tid & 1;                   // 0: hi plane, 1: lo plane

    // cp.async addresses for K/V tiles (prepacked rows: 128 u32 = hi|lo)
    const uint32_t kdst0 = smb + (uint32_t)(64 * QP) * 4u;   // slot 0 K base
    const uint32_t rowoff = (uint32_t)(lr * QP + half * 64) * 4u;
    const uint32_t* kpr = kp + lr * 128 + half * 64;
    const uint32_t* vpr = vp + lr * 128 + half * 64;

    // issue one KV stage (kt) into slot
    auto issue_kv = [&](int kt, int slot) {
        const uint32_t kb = kdst0 + (uint32_t)(slot * 2 * KVSLOT) * 4u + rowoff;
        const uint32_t vb = kb + (uint32_t)KVSLOT * 4u;
        const uint32_t* ks = kpr + (long)kt * 64 * 128;
        const uint32_t* vs = vpr + (long)kt * 64 * 128;
        #pragma unroll
        for (int j = 0; j < 16; j++) {
            cp16(kb + j * 16, ks + j * 4);
            cp16(vb + j * 16, vs + j * 4);
        }
    };

    // Load Q tile (pre-scaled), split into hi/lo bf16 (once per CTA)
    {
        const int lc0 = half * 16;
        const float* src = qkv + (long)(q0 + lr) * QKV_OUT + h * HD;
        uint32_t* dst = q_s + lr * QP;
        #pragma unroll
        for (int jj = 0; jj < 4; jj++) {
            const int c16 = lc0 + 32 * jj;
            split16(src + c16, dst + (c16 >> 1), dst + (c16 >> 1) + 64,
                    0.08838834764831845f);
        }
    }

    // prologue: KV stage 0 into slot 0
    issue_kv(0, 0);
    CP_COMMIT();

    float o[16][4];
    #pragma unroll
    for (int i = 0; i < 16; i++)
        #pragma unroll
        for (int j = 0; j < 4; j++) o[i][j] = 0.0f;
    float m0 = -1e30f, m1 = -1e30f, l0 = 0.0f, l1 = 0.0f;

    const int row0 = q0 + wid * 16 + g;
    const int row1 = row0 + 8;

    for (int kt = 0; kt <= bq; kt++) {
        const int slot = kt & 1;
        CP_WAIT0();          // stage kt resident (everything outstanding done)
        __syncthreads();     // all threads see it; prev compute done with other slot

        if (kt < bq) issue_kv(kt + 1, slot ^ 1);   // overlaps compute below
        CP_COMMIT();

        const uint32_t* k_s = asm_ + 64 * QP + slot * 2 * KVSLOT;
        const uint32_t v_base = smb + (uint32_t)(64 * QP + slot * 2 * KVSLOT + KVSLOT) * 4u;

        // ---- S = Q K^T (3-term bf16) ----
        float s[8][4];
        #pragma unroll
        for (int nt = 0; nt < 8; nt++)
            #pragma unroll
            for (int j = 0; j < 4; j++) s[nt][j] = 0.0f;

        const uint32_t* qb = q_s + (wid * 16) * QP;
        #pragma unroll
        for (int ks = 0; ks < 8; ks++) {
            uint32_t ah[4], al[4];
            const int ro = g * QP + ks * 8 + t4;
            ah[0] = qb[ro];          ah[1] = qb[ro + 8 * QP];
            ah[2] = qb[ro + 4];      ah[3] = qb[ro + 8 * QP + 4];
            al[0] = qb[ro + 64];     al[1] = qb[ro + 8 * QP + 64];
            al[2] = qb[ro + 68];     al[3] = qb[ro + 8 * QP + 68];
            #pragma unroll
            for (int nt = 0; nt < 8; nt++) {
                const int rb = (nt * 8 + g) * QP + ks * 8 + t4;
                uint32_t bh[2] = { k_s[rb],      k_s[rb + 4]  };
                uint32_t bl[2] = { k_s[rb + 64], k_s[rb + 68] };
                mma_bf16(s[nt], ah, bh);
                mma_bf16(s[nt], ah, bl);
                mma_bf16(s[nt], al, bh);
            }
        }

        if (kt == bq) {
            #pragma unroll
            for (int nt = 0; nt < 8; nt++) {
                const int col = kt * 64 + nt * 8 + 2 * t4;
                if (col     > row0) s[nt][0] = -1e30f;
                if (col + 1 > row0) s[nt][1] = -1e30f;
                if (col     > row1) s[nt][2] = -1e30f;
                if (col + 1 > row1) s[nt][3] = -1e30f;
            }
        }

        float mt0 = -1e30f, mt1 = -1e30f;
        #pragma unroll
        for (int nt = 0; nt < 8; nt++) {
            mt0 = fmaxf(mt0, fmaxf(s[nt][0], s[nt][1]));
            mt1 = fmaxf(mt1, fmaxf(s[nt][2], s[nt][3]));
        }
        mt0 = fmaxf(mt0, __shfl_xor_sync(0xffffffffu, mt0, 1));
        mt0 = fmaxf(mt0, __shfl_xor_sync(0xffffffffu, mt0, 2));
        mt1 = fmaxf(mt1, __shfl_xor_sync(0xffffffffu, mt1, 1));
        mt1 = fmaxf(mt1, __shfl_xor_sync(0xffffffffu, mt1, 2));

        const float mn0 = fmaxf(m0, mt0), mn1 = fmaxf(m1, mt1);
        const float al0 = __expf(m0 - mn0), al1 = __expf(m1 - mn1);

        float ps0 = 0.0f, ps1 = 0.0f;
        #pragma unroll
        for (int nt = 0; nt < 8; nt++) {
            s[nt][0] = __expf(s[nt][0] - mn0);
            s[nt][1] = __expf(s[nt][1] - mn0);
            s[nt][2] = __expf(s[nt][2] - mn1);
            s[nt][3] = __expf(s[nt][3] - mn1);
            ps0 += s[nt][0] + s[nt][1];
            ps1 += s[nt][2] + s[nt][3];
        }
        ps0 += __shfl_xor_sync(0xffffffffu, ps0, 1);
        ps0 += __shfl_xor_sync(0xffffffffu, ps0, 2);
        ps1 += __shfl_xor_sync(0xffffffffu, ps1, 1);
        ps1 += __shfl_xor_sync(0xffffffffu, ps1, 2);
        l0 = l0 * al0 + ps0; m0 = mn0;
        l1 = l1 * al1 + ps1; m1 = mn1;

        #pragma unroll
        for (int nt = 0; nt < 16; nt++) {
            o[nt][0] *= al0; o[nt][1] *= al0;
            o[nt][2] *= al1; o[nt][3] *= al1;
        }

        // ---- O += P V (3-term bf16) ----
        #pragma unroll
        for (int jj = 0; jj < 4; jj++) {
            uint32_t ph[4], pl[4];
            pack_split2(s[2*jj][0],   s[2*jj][1],   ph[0], pl[0]);
            pack_split2(s[2*jj][2],   s[2*jj][3],   ph[1], pl[1]);
            pack_split2(s[2*jj+1][0], s[2*jj+1][1], ph[2], pl[2]);
            pack_split2(s[2*jj+1][2], s[2*jj+1][3], ph[3], pl[3]);

            const uint32_t rowaddr = v_base + (uint32_t)(((jj * 16 + (lid & 15)) * QP) * 4);
            #pragma unroll
            for (int nt = 0; nt < 16; nt++) {
                uint32_t bh[2], bl[2];
                ldsm_x2_t(bh[0], bh[1], rowaddr + nt * 16);
                ldsm_x2_t(bl[0], bl[1], rowaddr + 256 + nt * 16);
                mma_bf16(o[nt], ph, bh);
                mma_bf16(o[nt], ph, bl);
                mma_bf16(o[nt], pl, bh);
            }
        }
    }

    const float i0 = 1.0f / l0, i1 = 1.0f / l1;
    #pragma unroll
    for (int nt = 0; nt < 16; nt++) {
        const int d = nt * 8 + 2 * t4;
        float2 a, b;
        a.x = o[nt][0] * i0; a.y = o[nt][1] * i0;
        b.x = o[nt][2] * i1; b.y = o[nt][3] * i1;
        *(float2*)&attn_out[(long)row0 * HID + h * HD + d] = a;
        *(float2*)&attn_out[(long)row1 * HID + h * HD + d] = b;
    }
}

// ---------------------------------------------------------------------------
extern "C" void kernel_launch(void* const* d_in, const int* in_sizes, int n_in,
                              void* d_out, int out_size)
{
    const float* x    = (const float*)d_in[0];
    const float* wqkv = (const float*)d_in[1];
    const float* bqkv = (const float*)d_in[2];
    const float* wo   = (const float*)d_in[3];
    const float* bo   = (const float*)d_in[4];
    float* out = (float*)d_out;

    float   *qkv_buf, *attn_buf;
    __half  *wh, *woh, *ah;
    uint32_t *kpb, *vpb;
    cudaGetSymbolAddress((void**)&qkv_buf,  g_qkv);
    cudaGetSymbolAddress((void**)&attn_buf, g_attn);
    cudaGetSymbolAddress((void**)&wh,  g_wh);
    cudaGetSymbolAddress((void**)&woh, g_woh);
    cudaGetSymbolAddress((void**)&ah,  g_ah);
    cudaGetSymbolAddress((void**)&kpb, g_kp);
    cudaGetSymbolAddress((void**)&vpb, g_vp);

    const int gemm_smem = 4 * STG_B;                            // 81920
    cudaFuncSetAttribute(gemm_f16a,
                         cudaFuncAttributeMaxDynamicSharedMemorySize, gemm_smem);
    const int attn_smem = 5 * 64 * QP * sizeof(uint32_t);       // 168960
    cudaFuncSetAttribute(mqa_flash_hmma,
                         cudaFuncAttributeMaxDynamicSharedMemorySize, attn_smem);

    // 0) conversions (weights + input activations)
    {
        int n4 = (QKV_OUT * HID) / 4;
        f32_to_f16_k<<<(n4 + 255) / 256, 256>>>(wqkv, wh, n4);
        n4 = (HID * HID) / 4;
        f32_to_f16_k<<<(n4 + 255) / 256, 256>>>(wo, woh, n4);
        n4 = (S_LEN * HID) / 4;
        f32_to_f16_k<<<(n4 + 255) / 256, 256>>>(x, ah, n4);
    }

    // 1) QKV projection
    {
        dim3 grid(QKV_OUT / 128, S_LEN / 128);
        gemm_f16a<<<grid, 256, gemm_smem>>>(ah, wh, bqkv, qkv_buf, QKV_OUT);
    }
    // 1b) prepack K/V bf16 planes (once; shared by all 48 heads)
    {
        kv_prepack_k<<<(S_LEN * 8 + 255) / 256, 256>>>(qkv_buf, kpb, vpb);
    }
    // 2) attention
    {
        dim3 grid(S_LEN / 64, NH);
        mqa_flash_hmma<<<grid, 128, attn_smem>>>(qkv_buf, kpb, vpb, attn_buf);
    }
    // 3) convert attention output, then output projection
    {
        int n4 = (S_LEN * HID) / 4;
        f32_to_f16_k<<<(n4 + 255) / 256, 256>>>(attn_buf, ah, n4);
        dim3 grid(HID / 128, S_LEN / 128);
        gemm_f16a<<<grid, 256, gemm_smem>>>(ah, woh, bo, out, HID);
    }
}

// round 13
// speedup vs baseline: 1.0374x; 1.0374x over previous
#include <cuda_runtime.h>
#include <cuda_bf16.h>
#include <cuda_fp16.h>
#include <cstdint>

// Problem constants (B=1 fixed)
#define S_LEN   2048
#define HID     6144
#define QKV_OUT 6400   // HID + 2*128
#define NH      48
#define HD      128
#define KDIM    6144   // GEMM K (both projections)

// Scratch (no cudaMalloc allowed)
__device__ float    g_qkv [S_LEN * QKV_OUT];
__device__ float    g_attn[S_LEN * HID];
__device__ __half   g_wh  [QKV_OUT * HID];   // wqkv fp16
__device__ __half   g_woh [HID * HID];       // wo fp16
__device__ __half   g_ah  [S_LEN * HID];     // activation fp16
__device__ uint32_t g_kp  [S_LEN * 128];     // K bf16 hi|lo planes (packed pairs)
__device__ uint32_t g_vp  [S_LEN * 128];     // V bf16 hi|lo planes

// ---------------------------------------------------------------------------
// helpers
// ---------------------------------------------------------------------------
__device__ __forceinline__ uint32_t smem_u32(const void* p) {
    uint32_t a;
    asm("{ .reg .u64 t; cvta.to.shared.u64 t, %1; cvt.u32.u64 %0, t; }"
        : "=r"(a) : "l"(p));
    return a;
}

__device__ __forceinline__ void cp16(uint32_t dst, const void* src) {
    asm volatile("cp.async.cg.shared.global [%0], [%1], 16;"
                 :: "r"(dst), "l"(src) : "memory");
}
#define CP_COMMIT() asm volatile("cp.async.commit_group;" ::: "memory")
#define CP_WAIT2()  asm volatile("cp.async.wait_group 2;" ::: "memory")

__device__ __forceinline__ void mma_bf16(float* d, const uint32_t* a, const uint32_t* b) {
    asm volatile(
        "mma.sync.aligned.m16n8k16.row.col.f32.bf16.bf16.f32 "
        "{%0,%1,%2,%3}, {%4,%5,%6,%7}, {%8,%9}, {%0,%1,%2,%3};"
        : "+f"(d[0]), "+f"(d[1]), "+f"(d[2]), "+f"(d[3])
        : "r"(a[0]), "r"(a[1]), "r"(a[2]), "r"(a[3]), "r"(b[0]), "r"(b[1]));
}
__device__ __forceinline__ void mma_f16(float* d, const uint32_t* a, const uint32_t* b) {
    asm volatile(
        "mma.sync.aligned.m16n8k16.row.col.f32.f16.f16.f32 "
        "{%0,%1,%2,%3}, {%4,%5,%6,%7}, {%8,%9}, {%0,%1,%2,%3};"
        : "+f"(d[0]), "+f"(d[1]), "+f"(d[2]), "+f"(d[3])
        : "r"(a[0]), "r"(a[1]), "r"(a[2]), "r"(a[3]), "r"(b[0]), "r"(b[1]));
}

__device__ __forceinline__ void ldsm_x4(uint32_t* r, uint32_t addr) {
    asm volatile("ldmatrix.sync.aligned.m8n8.x4.shared.b16 {%0,%1,%2,%3}, [%4];"
                 : "=r"(r[0]), "=r"(r[1]), "=r"(r[2]), "=r"(r[3]) : "r"(addr));
}
__device__ __forceinline__ void ldsm_x2(uint32_t* r, uint32_t addr) {
    asm volatile("ldmatrix.sync.aligned.m8n8.x2.shared.b16 {%0,%1}, [%2];"
                 : "=r"(r[0]), "=r"(r[1]) : "r"(addr));
}
__device__ __forceinline__ void ldsm_x2_t(uint32_t& r0, uint32_t& r1, uint32_t addr) {
    asm volatile("ldmatrix.sync.aligned.m8n8.x2.trans.shared.b16 {%0,%1}, [%2];"
                 : "=r"(r0), "=r"(r1) : "r"(addr));
}

// ---- bf16 split helpers ----
__device__ __forceinline__ void pack_split2(float x, float y, uint32_t& hi, uint32_t& lo) {
    __nv_bfloat162 h = __floats2bfloat162_rn(x, y);
    float2 hf = __bfloat1622float2(h);
    __nv_bfloat162 l = __floats2bfloat162_rn(x - hf.x, y - hf.y);
    hi = *reinterpret_cast<uint32_t*>(&h);
    lo = *reinterpret_cast<uint32_t*>(&l);
}
__device__ __forceinline__ void split16(const float* src, uint32_t* hi, uint32_t* lo,
                                        float scale) {
    #pragma unroll
    for (int i = 0; i < 4; i++) {
        float4 f = *(const float4*)(src + i * 4);
        f.x *= scale; f.y *= scale; f.z *= scale; f.w *= scale;
        uint32_t h0, l0, h1, l1;
        pack_split2(f.x, f.y, h0, l0);
        pack_split2(f.z, f.w, h1, l1);
        hi[i * 2] = h0; hi[i * 2 + 1] = h1;
        lo[i * 2] = l0; lo[i * 2 + 1] = l1;
    }
}

// ---------------------------------------------------------------------------
// conversion / prepack kernels (run once per launch)
// ---------------------------------------------------------------------------
__global__ void __launch_bounds__(256) f32_to_f16_k(const float* __restrict__ in,
                                                    __half* __restrict__ out, int n4) {
    const int i = blockIdx.x * 256 + threadIdx.x;
    if (i < n4) {
        float4 f = ((const float4*)in)[i];
        __half2 a = __floats2half2_rn(f.x, f.y);
        __half2 b = __floats2half2_rn(f.z, f.w);
        ((uint2*)out)[i] = make_uint2(*reinterpret_cast<uint32_t*>(&a),
                                      *reinterpret_cast<uint32_t*>(&b));
    }
}

// split K/V rows of qkv into bf16 hi/lo planes (once; shared by all 48 heads)
__global__ void __launch_bounds__(256) kv_prepack_k(const float* __restrict__ qkv,
                                                    uint32_t* __restrict__ kp,
                                                    uint32_t* __restrict__ vp) {
    const int i = blockIdx.x * 256 + threadIdx.x;   // 0 .. 2048*8-1
    if (i < S_LEN * 8) {
        const int r = i >> 3, c16 = (i & 7) * 16;
        const float* src = qkv + (long)r * QKV_OUT + HID;
        split16(src + c16,      kp + r * 128 + (c16 >> 1), kp + r * 128 + (c16 >> 1) + 64, 1.0f);
        split16(src + HD + c16, vp + r * 128 + (c16 >> 1), vp + r * 128 + (c16 >> 1) + 64, 1.0f);
    }
}

// ---------------------------------------------------------------------------
// fp16 async GEMM: C[M,N] = Ah[M,K] * Bh[N,K]^T + bias[N]  (K=6144)
// CTA 128x128, BK=32, 256 threads, warp tile 64x32, 4-stage cp.async ring.
// Tile pitch 80B. 2 CTAs/SM.  (R12 version — measured 566us)
// ---------------------------------------------------------------------------
#define TILE_B 10240
#define STG_B  (2 * TILE_B)
#define NSTG   (KDIM / 32)

__global__ void __launch_bounds__(256, 2) gemm_f16a(
    const __half* __restrict__ Ah, const __half* __restrict__ Bh,
    const float* __restrict__ bias, float* __restrict__ C, int N)
{
    extern __shared__ char gsm[];
    const uint32_t smb = smem_u32(gsm);

    const int tid = threadIdx.x;
    const int wid = tid >> 5, lid = tid & 31;
    const int g   = lid >> 2;
    const int t4  = lid & 3;
    const int wr  = wid >> 2;
    const int wc  = wid & 3;

    const int bm = blockIdx.y * 128, bn = blockIdx.x * 128;

    const int lrow = tid >> 1;
    const int lel  = (tid & 1) * 16;
    const __half* Ag = Ah + (long)(bm + lrow) * KDIM + lel;
    const __half* Bg = Bh + (long)(bn + lrow) * KDIM + lel;
    const uint32_t sdst = smb + (uint32_t)(lrow * 80 + lel * 2);

    const uint32_t a_row = (uint32_t)((wr * 64 + (lid & 15)) * 80 + (lid >> 4) * 16);
    const uint32_t b_row = (uint32_t)((wc * 32 + (lid & 7)) * 80 + ((lid >> 3) & 1) * 16);

    float acc[4][4][4];
    #pragma unroll
    for (int i = 0; i < 4; i++)
        #pragma unroll
        for (int j = 0; j < 4; j++)
            #pragma unroll
            for (int k = 0; k < 4; k++) acc[i][j][k] = 0.0f;

    #pragma unroll
    for (int s = 0; s < 3; s++) {
        const uint32_t sb = sdst + s * STG_B;
        const long go = (long)s * 32;
        cp16(sb,          Ag + go);  cp16(sb + 16,          Ag + go + 8);
        cp16(sb + TILE_B, Bg + go);  cp16(sb + TILE_B + 16, Bg + go + 8);
        CP_COMMIT();
    }

    int slot = 0;
    for (int s = 0; s < NSTG; s++) {
        CP_WAIT2();
        __syncthreads();

        if (s + 3 < NSTG) {
            const int wslot = (slot + 3) & 3;
            const uint32_t sb = sdst + wslot * STG_B;
            const long go = (long)(s + 3) * 32;
            cp16(sb,          Ag + go);  cp16(sb + 16,          Ag + go + 8);
            cp16(sb + TILE_B, Bg + go);  cp16(sb + TILE_B + 16, Bg + go + 8);
        }
        CP_COMMIT();

        const uint32_t abase = smb + slot * STG_B + a_row;
        const uint32_t bbase = smb + slot * STG_B + TILE_B + b_row;

        #pragma unroll
        for (int ks = 0; ks < 2; ks++) {
            uint32_t ah[4][4];
            #pragma unroll
            for (int mt = 0; mt < 4; mt++)
                ldsm_x4(ah[mt], abase + ks * 32 + mt * (16 * 80));
            #pragma unroll
            for (int nt = 0; nt < 4; nt++) {
                uint32_t bh[2];
                ldsm_x2(bh, bbase + ks * 32 + nt * (8 * 80));
                #pragma unroll
                for (int mt = 0; mt < 4; mt++) mma_f16(acc[mt][nt], ah[mt], bh);
            }
        }

        slot = (slot + 1) & 3;
    }

    #pragma unroll
    for (int mt = 0; mt < 4; mt++) {
        const int row = bm + wr * 64 + mt * 16 + g;
        #pragma unroll
        for (int nt = 0; nt < 4; nt++) {
            const int col = bn + wc * 32 + nt * 8 + t4 * 2;
            const float b0 = bias[col], b1 = bias[col + 1];
            float2 lo, hi;
            lo.x = acc[mt][nt][0] + b0; lo.y = acc[mt][nt][1] + b1;
            hi.x = acc[mt][nt][2] + b0; hi.y = acc[mt][nt][3] + b1;
            *(float2*)&C[(long)row * N + col]       = lo;
            *(float2*)&C[(long)(row + 8) * N + col] = hi;
        }
    }
}

// ---------------------------------------------------------------------------
// MQA causal flash attention, bf16-split HMMA. R11 sync structure (measured
// 650us) but K/V loaded as prepacked bf16 planes via plain uint4 copies
// (no per-head re-split). CTA: 128 threads, BQ=64, BKV=64.
// ---------------------------------------------------------------------------
#define QP 132

__global__ void __launch_bounds__(128) mqa_flash_hmma(
    const float* __restrict__ qkv,
    const uint32_t* __restrict__ kp, const uint32_t* __restrict__ vp,
    float* __restrict__ attn_out)
{
    extern __shared__ uint32_t asm_[];
    uint32_t* q_s = asm_;                 // [64][QP]
    uint32_t* k_s = q_s + 64 * QP;
    uint32_t* v_s = k_s + 64 * QP;

    const int h  = blockIdx.y;
    const int bq = blockIdx.x;
    const int q0 = bq * 64;
    const int tid = threadIdx.x;
    const int wid = tid >> 5, lid = tid & 31;
    const int g = lid >> 2, t4 = lid & 3;

    const uint32_t v_base = smem_u32(v_s);

    // Q loader (once): 2 threads per row, split fp32 -> bf16 hi/lo
    {
        const int lr  = tid >> 1;
        const int lc0 = (tid & 1) * 16;
        const float* src = qkv + (long)(q0 + lr) * QKV_OUT + h * HD;
        uint32_t* dst = q_s + lr * QP;
        #pragma unroll
        for (int jj = 0; jj < 4; jj++) {
            const int c16 = lc0 + 32 * jj;
            split16(src + c16, dst + (c16 >> 1), dst + (c16 >> 1) + 64,
                    0.08838834764831845f);
        }
    }

    // K/V copy mapping: threads 0-63 -> K row t; 64-127 -> V row t-64.
    const int iskv = tid >> 6;             // 0: K, 1: V
    const int krow = tid & 63;
    const uint32_t* gsrc = (iskv ? vp : kp) + krow * 128;
    uint32_t* sdst = (iskv ? v_s : k_s) + krow * QP;

    float o[16][4];
    #pragma unroll
    for (int i = 0; i < 16; i++)
        #pragma unroll
        for (int j = 0; j < 4; j++) o[i][j] = 0.0f;
    float m0 = -1e30f, m1 = -1e30f, l0 = 0.0f, l1 = 0.0f;

    const int row0 = q0 + wid * 16 + g;
    const int row1 = row0 + 8;

    for (int kt = 0; kt <= bq; kt++) {
        __syncthreads();   // previous tile's smem reads done / Q ready
        {
            const uint32_t* src = gsrc + (long)kt * 64 * 128;
            #pragma unroll
            for (int j = 0; j < 32; j++) {
                uint4 t = __ldg((const uint4*)(src + j * 4));
                *(uint4*)(sdst + j * 4) = t;
            }
        }
        __syncthreads();

        // ---- S = Q K^T (3-term bf16) ----
        float s[8][4];
        #pragma unroll
        for (int nt = 0; nt < 8; nt++)
            #pragma unroll
            for (int j = 0; j < 4; j++) s[nt][j] = 0.0f;

        const uint32_t* qb = q_s + (wid * 16) * QP;
        #pragma unroll
        for (int ks = 0; ks < 8; ks++) {
            uint32_t ah[4], al[4];
            const int ro = g * QP + ks * 8 + t4;
            ah[0] = qb[ro];          ah[1] = qb[ro + 8 * QP];
            ah[2] = qb[ro + 4];      ah[3] = qb[ro + 8 * QP + 4];
            al[0] = qb[ro + 64];     al[1] = qb[ro + 8 * QP + 64];
            al[2] = qb[ro + 68];     al[3] = qb[ro + 8 * QP + 68];
            #pragma unroll
            for (int nt = 0; nt < 8; nt++) {
                const int rb = (nt * 8 + g) * QP + ks * 8 + t4;
                uint32_t bh[2] = { k_s[rb],      k_s[rb + 4]  };
                uint32_t bl[2] = { k_s[rb + 64], k_s[rb + 68] };
                mma_bf16(s[nt], ah, bh);
                mma_bf16(s[nt], ah, bl);
                mma_bf16(s[nt], al, bh);
            }
        }

        if (kt == bq) {
            #pragma unroll
            for (int nt = 0; nt < 8; nt++) {
                const int col = kt * 64 + nt * 8 + 2 * t4;
                if (col     > row0) s[nt][0] = -1e30f;
                if (col + 1 > row0) s[nt][1] = -1e30f;
                if (col     > row1) s[nt][2] = -1e30f;
                if (col + 1 > row1) s[nt][3] = -1e30f;
            }
        }

        float mt0 = -1e30f, mt1 = -1e30f;
        #pragma unroll
        for (int nt = 0; nt < 8; nt++) {
            mt0 = fmaxf(mt0, fmaxf(s[nt][0], s[nt][1]));
            mt1 = fmaxf(mt1, fmaxf(s[nt][2], s[nt][3]));
        }
        mt0 = fmaxf(mt0, __shfl_xor_sync(0xffffffffu, mt0, 1));
        mt0 = fmaxf(mt0, __shfl_xor_sync(0xffffffffu, mt0, 2));
        mt1 = fmaxf(mt1, __shfl_xor_sync(0xffffffffu, mt1, 1));
        mt1 = fmaxf(mt1, __shfl_xor_sync(0xffffffffu, mt1, 2));

        const float mn0 = fmaxf(m0, mt0), mn1 = fmaxf(m1, mt1);
        const float al0 = __expf(m0 - mn0), al1 = __expf(m1 - mn1);

        float ps0 = 0.0f, ps1 = 0.0f;
        #pragma unroll
        for (int nt = 0; nt < 8; nt++) {
            s[nt][0] = __expf(s[nt][0] - mn0);
            s[nt][1] = __expf(s[nt][1] - mn0);
            s[nt][2] = __expf(s[nt][2] - mn1);
            s[nt][3] = __expf(s[nt][3] - mn1);
            ps0 += s[nt][0] + s[nt][1];
            ps1 += s[nt][2] + s[nt][3];
        }
        ps0 += __shfl_xor_sync(0xffffffffu, ps0, 1);
        ps0 += __shfl_xor_sync(0xffffffffu, ps0, 2);
        ps1 += __shfl_xor_sync(0xffffffffu, ps1, 1);
        ps1 += __shfl_xor_sync(0xffffffffu, ps1, 2);
        l0 = l0 * al0 + ps0; m0 = mn0;
        l1 = l1 * al1 + ps1; m1 = mn1;

        #pragma unroll
        for (int nt = 0; nt < 16; nt++) {
            o[nt][0] *= al0; o[nt][1] *= al0;
            o[nt][2] *= al1; o[nt][3] *= al1;
        }

        // ---- O += P V (3-term bf16) ----
        #pragma unroll
        for (int jj = 0; jj < 4; jj++) {
            uint32_t ph[4], pl[4];
            pack_split2(s[2*jj][0],   s[2*jj][1],   ph[0], pl[0]);
            pack_split2(s[2*jj][2],   s[2*jj][3],   ph[1], pl[1]);
            pack_split2(s[2*jj+1][0], s[2*jj+1][1], ph[2], pl[2]);
            pack_split2(s[2*jj+1][2], s[2*jj+1][3], ph[3], pl[3]);

            const uint32_t rowaddr = v_base + (uint32_t)(((jj * 16 + (lid & 15)) * QP) * 4);
            #pragma unroll
            for (int nt = 0; nt < 16; nt++) {
                uint32_t bh[2], bl[2];
                ldsm_x2_t(bh[0], bh[1], rowaddr + nt * 16);
                ldsm_x2_t(bl[0], bl[1], rowaddr + 256 + nt * 16);
                mma_bf16(o[nt], ph, bh);
                mma_bf16(o[nt], ph, bl);
                mma_bf16(o[nt], pl, bh);
            }
        }
    }

    const float i0 = 1.0f / l0, i1 = 1.0f / l1;
    #pragma unroll
    for (int nt = 0; nt < 16; nt++) {
        const int d = nt * 8 + 2 * t4;
        float2 a, b;
        a.x = o[nt][0] * i0; a.y = o[nt][1] * i0;
        b.x = o[nt][2] * i1; b.y = o[nt][3] * i1;
        *(float2*)&attn_out[(long)row0 * HID + h * HD + d] = a;
        *(float2*)&attn_out[(long)row1 * HID + h * HD + d] = b;
    }
}

// ---------------------------------------------------------------------------
extern "C" void kernel_launch(void* const* d_in, const int* in_sizes, int n_in,
                              void* d_out, int out_size)
{
    const float* x    = (const float*)d_in[0];
    const float* wqkv = (const float*)d_in[1];
    const float* bqkv = (const float*)d_in[2];
    const float* wo   = (const float*)d_in[3];
    const float* bo   = (const float*)d_in[4];
    float* out = (float*)d_out;

    float   *qkv_buf, *attn_buf;
    __half  *wh, *woh, *ah;
    uint32_t *kpb, *vpb;
    cudaGetSymbolAddress((void**)&qkv_buf,  g_qkv);
    cudaGetSymbolAddress((void**)&attn_buf, g_attn);
    cudaGetSymbolAddress((void**)&wh,  g_wh);
    cudaGetSymbolAddress((void**)&woh, g_woh);
    cudaGetSymbolAddress((void**)&ah,  g_ah);
    cudaGetSymbolAddress((void**)&kpb, g_kp);
    cudaGetSymbolAddress((void**)&vpb, g_vp);

    const int gemm_smem = 4 * STG_B;                            // 81920
    cudaFuncSetAttribute(gemm_f16a,
                         cudaFuncAttributeMaxDynamicSharedMemorySize, gemm_smem);
    const int attn_smem = 3 * 64 * QP * sizeof(uint32_t);       // 101376
    cudaFuncSetAttribute(mqa_flash_hmma,
                         cudaFuncAttributeMaxDynamicSharedMemorySize, attn_smem);

    // 0) conversions (weights + input activations)
    {
        int n4 = (QKV_OUT * HID) / 4;
        f32_to_f16_k<<<(n4 + 255) / 256, 256>>>(wqkv, wh, n4);
        n4 = (HID * HID) / 4;
        f32_to_f16_k<<<(n4 + 255) / 256, 256>>>(wo, woh, n4);
        n4 = (S_LEN * HID) / 4;
        f32_to_f16_k<<<(n4 + 255) / 256, 256>>>(x, ah, n4);
    }

    // 1) QKV projection
    {
        dim3 grid(QKV_OUT / 128, S_LEN / 128);
        gemm_f16a<<<grid, 256, gemm_smem>>>(ah, wh, bqkv, qkv_buf, QKV_OUT);
    }
    // 1b) prepack K/V bf16 planes (once; shared by all 48 heads)
    {
        kv_prepack_k<<<(S_LEN * 8 + 255) / 256, 256>>>(qkv_buf, kpb, vpb);
    }
    // 2) attention
    {
        dim3 grid(S_LEN / 64, NH);
        mqa_flash_hmma<<<grid, 128, attn_smem>>>(qkv_buf, kpb, vpb, attn_buf);
    }
    // 3) convert attention output, then output projection
    {
        int n4 = (S_LEN * HID) / 4;
        f32_to_f16_k<<<(n4 + 255) / 256, 256>>>(attn_buf, ah, n4);
        dim3 grid(HID / 128, S_LEN / 128);
        gemm_f16a<<<grid, 256, gemm_smem>>>(ah, woh, bo, out, HID);
    }
}

// round 14
// speedup vs baseline: 1.2099x; 1.1663x over previous
#include <cuda_runtime.h>
#include <cuda_bf16.h>
#include <cuda_fp16.h>
#include <cstdint>

// Problem constants (B=1 fixed)
#define S_LEN   2048
#define HID     6144
#define QKV_OUT 6400   // HID + 2*128
#define NH      48
#define HD      128
#define KDIM    6144   // GEMM K (both projections)

// Scratch (no cudaMalloc allowed)
__device__ float  g_qkv [S_LEN * QKV_OUT];
__device__ __half g_wh  [QKV_OUT * HID];   // wqkv fp16
__device__ __half g_woh [HID * HID];       // wo fp16
__device__ __half g_ah  [S_LEN * HID];     // activation fp16 (GEMM A operand)

// ---------------------------------------------------------------------------
// helpers
// ---------------------------------------------------------------------------
__device__ __forceinline__ uint32_t smem_u32(const void* p) {
    uint32_t a;
    asm("{ .reg .u64 t; cvta.to.shared.u64 t, %1; cvt.u32.u64 %0, t; }"
        : "=r"(a) : "l"(p));
    return a;
}

__device__ __forceinline__ void cp16(uint32_t dst, const void* src) {
    asm volatile("cp.async.cg.shared.global [%0], [%1], 16;"
                 :: "r"(dst), "l"(src) : "memory");
}
#define CP_COMMIT() asm volatile("cp.async.commit_group;" ::: "memory")
#define CP_WAIT2()  asm volatile("cp.async.wait_group 2;" ::: "memory")

__device__ __forceinline__ void mma_bf16(float* d, const uint32_t* a, const uint32_t* b) {
    asm volatile(
        "mma.sync.aligned.m16n8k16.row.col.f32.bf16.bf16.f32 "
        "{%0,%1,%2,%3}, {%4,%5,%6,%7}, {%8,%9}, {%0,%1,%2,%3};"
        : "+f"(d[0]), "+f"(d[1]), "+f"(d[2]), "+f"(d[3])
        : "r"(a[0]), "r"(a[1]), "r"(a[2]), "r"(a[3]), "r"(b[0]), "r"(b[1]));
}
__device__ __forceinline__ void mma_f16(float* d, const uint32_t* a, const uint32_t* b) {
    asm volatile(
        "mma.sync.aligned.m16n8k16.row.col.f32.f16.f16.f32 "
        "{%0,%1,%2,%3}, {%4,%5,%6,%7}, {%8,%9}, {%0,%1,%2,%3};"
        : "+f"(d[0]), "+f"(d[1]), "+f"(d[2]), "+f"(d[3])
        : "r"(a[0]), "r"(a[1]), "r"(a[2]), "r"(a[3]), "r"(b[0]), "r"(b[1]));
}

__device__ __forceinline__ void ldsm_x4(uint32_t* r, uint32_t addr) {
    asm volatile("ldmatrix.sync.aligned.m8n8.x4.shared.b16 {%0,%1,%2,%3}, [%4];"
                 : "=r"(r[0]), "=r"(r[1]), "=r"(r[2]), "=r"(r[3]) : "r"(addr));
}
__device__ __forceinline__ void ldsm_x2(uint32_t* r, uint32_t addr) {
    asm volatile("ldmatrix.sync.aligned.m8n8.x2.shared.b16 {%0,%1}, [%2];"
                 : "=r"(r[0]), "=r"(r[1]) : "r"(addr));
}
__device__ __forceinline__ void ldsm_x2_t(uint32_t& r0, uint32_t& r1, uint32_t addr) {
    asm volatile("ldmatrix.sync.aligned.m8n8.x2.trans.shared.b16 {%0,%1}, [%2];"
                 : "=r"(r0), "=r"(r1) : "r"(addr));
}

// ---- bf16 split helpers (attention) ----
__device__ __forceinline__ void pack_split2(float x, float y, uint32_t& hi, uint32_t& lo) {
    __nv_bfloat162 h = __floats2bfloat162_rn(x, y);
    float2 hf = __bfloat1622float2(h);
    __nv_bfloat162 l = __floats2bfloat162_rn(x - hf.x, y - hf.y);
    hi = *reinterpret_cast<uint32_t*>(&h);
    lo = *reinterpret_cast<uint32_t*>(&l);
}
__device__ __forceinline__ void split16(const float* src, uint32_t* hi, uint32_t* lo,
                                        float scale) {
    #pragma unroll
    for (int i = 0; i < 4; i++) {
        float4 f = *(const float4*)(src + i * 4);
        f.x *= scale; f.y *= scale; f.z *= scale; f.w *= scale;
        uint32_t h0, l0, h1, l1;
        pack_split2(f.x, f.y, h0, l0);
        pack_split2(f.z, f.w, h1, l1);
        hi[i * 2] = h0; hi[i * 2 + 1] = h1;
        lo[i * 2] = l0; lo[i * 2 + 1] = l1;
    }
}

// ---------------------------------------------------------------------------
// conversion kernel (weights + input activations)
// ---------------------------------------------------------------------------
__global__ void __launch_bounds__(256) f32_to_f16_k(const float* __restrict__ in,
                                                    __half* __restrict__ out, int n4) {
    const int i = blockIdx.x * 256 + threadIdx.x;
    if (i < n4) {
        float4 f = ((const float4*)in)[i];
        __half2 a = __floats2half2_rn(f.x, f.y);
        __half2 b = __floats2half2_rn(f.z, f.w);
        ((uint2*)out)[i] = make_uint2(*reinterpret_cast<uint32_t*>(&a),
                                      *reinterpret_cast<uint32_t*>(&b));
    }
}

// ---------------------------------------------------------------------------
// fp16 async GEMM: C[M,N] = Ah[M,K] * Bh[N,K]^T + bias[N]  (K=6144)
// CTA 128x128, BK=32, 256 threads, warp tile 64x32, 4-stage cp.async ring.
// Tile pitch 80B. 2 CTAs/SM.  (R12 version — measured 565us)
// ---------------------------------------------------------------------------
#define TILE_B 10240
#define STG_B  (2 * TILE_B)
#define NSTG   (KDIM / 32)

__global__ void __launch_bounds__(256, 2) gemm_f16a(
    const __half* __restrict__ Ah, const __half* __restrict__ Bh,
    const float* __restrict__ bias, float* __restrict__ C, int N)
{
    extern __shared__ char gsm[];
    const uint32_t smb = smem_u32(gsm);

    const int tid = threadIdx.x;
    const int wid = tid >> 5, lid = tid & 31;
    const int g   = lid >> 2;
    const int t4  = lid & 3;
    const int wr  = wid >> 2;
    const int wc  = wid & 3;

    const int bm = blockIdx.y * 128, bn = blockIdx.x * 128;

    const int lrow = tid >> 1;
    const int lel  = (tid & 1) * 16;
    const __half* Ag = Ah + (long)(bm + lrow) * KDIM + lel;
    const __half* Bg = Bh + (long)(bn + lrow) * KDIM + lel;
    const uint32_t sdst = smb + (uint32_t)(lrow * 80 + lel * 2);

    const uint32_t a_row = (uint32_t)((wr * 64 + (lid & 15)) * 80 + (lid >> 4) * 16);
    const uint32_t b_row = (uint32_t)((wc * 32 + (lid & 7)) * 80 + ((lid >> 3) & 1) * 16);

    float acc[4][4][4];
    #pragma unroll
    for (int i = 0; i < 4; i++)
        #pragma unroll
        for (int j = 0; j < 4; j++)
            #pragma unroll
            for (int k = 0; k < 4; k++) acc[i][j][k] = 0.0f;

    #pragma unroll
    for (int s = 0; s < 3; s++) {
        const uint32_t sb = sdst + s * STG_B;
        const long go = (long)s * 32;
        cp16(sb,          Ag + go);  cp16(sb + 16,          Ag + go + 8);
        cp16(sb + TILE_B, Bg + go);  cp16(sb + TILE_B + 16, Bg + go + 8);
        CP_COMMIT();
    }

    int slot = 0;
    for (int s = 0; s < NSTG; s++) {
        CP_WAIT2();
        __syncthreads();

        if (s + 3 < NSTG) {
            const int wslot = (slot + 3) & 3;
            const uint32_t sb = sdst + wslot * STG_B;
            const long go = (long)(s + 3) * 32;
            cp16(sb,          Ag + go);  cp16(sb + 16,          Ag + go + 8);
            cp16(sb + TILE_B, Bg + go);  cp16(sb + TILE_B + 16, Bg + go + 8);
        }
        CP_COMMIT();

        const uint32_t abase = smb + slot * STG_B + a_row;
        const uint32_t bbase = smb + slot * STG_B + TILE_B + b_row;

        #pragma unroll
        for (int ks = 0; ks < 2; ks++) {
            uint32_t ah[4][4];
            #pragma unroll
            for (int mt = 0; mt < 4; mt++)
                ldsm_x4(ah[mt], abase + ks * 32 + mt * (16 * 80));
            #pragma unroll
            for (int nt = 0; nt < 4; nt++) {
                uint32_t bh[2];
                ldsm_x2(bh, bbase + ks * 32 + nt * (8 * 80));
                #pragma unroll
                for (int mt = 0; mt < 4; mt++) mma_f16(acc[mt][nt], ah[mt], bh);
            }
        }

        slot = (slot + 1) & 3;
    }

    #pragma unroll
    for (int mt = 0; mt < 4; mt++) {
        const int row = bm + wr * 64 + mt * 16 + g;
        #pragma unroll
        for (int nt = 0; nt < 4; nt++) {
            const int col = bn + wc * 32 + nt * 8 + t4 * 2;
            const float b0 = bias[col], b1 = bias[col + 1];
            float2 lo, hi;
            lo.x = acc[mt][nt][0] + b0; lo.y = acc[mt][nt][1] + b1;
            hi.x = acc[mt][nt][2] + b0; hi.y = acc[mt][nt][3] + b1;
            *(float2*)&C[(long)row * N + col]       = lo;
            *(float2*)&C[(long)(row + 8) * N + col] = hi;
        }
    }
}

// ---------------------------------------------------------------------------
// MQA causal flash attention, bf16-split HMMA (exact R11 loop — measured 650us).
// Epilogue writes fp16 directly into g_ah (GEMM3's A operand).
// CTA: 128 threads, BQ=64, BKV=64, D=128.
// ---------------------------------------------------------------------------
#define QP 132

__global__ void __launch_bounds__(128) mqa_flash_hmma(
    const float* __restrict__ qkv, __half* __restrict__ attn_h)
{
    extern __shared__ uint32_t asm_[];
    uint32_t* q_s = asm_;
    uint32_t* k_s = q_s + 64 * QP;
    uint32_t* v_s = k_s + 64 * QP;

    const int h  = blockIdx.y;
    const int bq = blockIdx.x;
    const int q0 = bq * 64;
    const int tid = threadIdx.x;
    const int wid = tid >> 5, lid = tid & 31;
    const int g = lid >> 2, t4 = lid & 3;

    const uint32_t v_base = smem_u32(v_s);

    const int lr  = tid >> 1;
    const int lc0 = (tid & 1) * 16;

    {
        const float* src = qkv + (long)(q0 + lr) * QKV_OUT + h * HD;
        uint32_t* dst = q_s + lr * QP;
        #pragma unroll
        for (int jj = 0; jj < 4; jj++) {
            const int c16 = lc0 + 32 * jj;
            split16(src + c16, dst + (c16 >> 1), dst + (c16 >> 1) + 64,
                    0.08838834764831845f);
        }
    }

    float o[16][4];
    #pragma unroll
    for (int i = 0; i < 16; i++)
        #pragma unroll
        for (int j = 0; j < 4; j++) o[i][j] = 0.0f;
    float m0 = -1e30f, m1 = -1e30f, l0 = 0.0f, l1 = 0.0f;

    const int row0 = q0 + wid * 16 + g;
    const int row1 = row0 + 8;

    for (int kt = 0; kt <= bq; kt++) {
        __syncthreads();
        {
            const float* kp = qkv + (long)(kt * 64 + lr) * QKV_OUT + HID;
            uint32_t* kd = k_s + lr * QP;
            uint32_t* vd = v_s + lr * QP;
            #pragma unroll
            for (int jj = 0; jj < 4; jj++) {
                const int c16 = lc0 + 32 * jj;
                split16(kp + c16,      kd + (c16 >> 1), kd + (c16 >> 1) + 64, 1.0f);
                split16(kp + HD + c16, vd + (c16 >> 1), vd + (c16 >> 1) + 64, 1.0f);
            }
        }
        __syncthreads();

        float s[8][4];
        #pragma unroll
        for (int nt = 0; nt < 8; nt++)
            #pragma unroll
            for (int j = 0; j < 4; j++) s[nt][j] = 0.0f;

        const uint32_t* qb = q_s + (wid * 16) * QP;
        #pragma unroll
        for (int ks = 0; ks < 8; ks++) {
            uint32_t ah[4], al[4];
            const int ro = g * QP + ks * 8 + t4;
            ah[0] = qb[ro];          ah[1] = qb[ro + 8 * QP];
            ah[2] = qb[ro + 4];      ah[3] = qb[ro + 8 * QP + 4];
            al[0] = qb[ro + 64];     al[1] = qb[ro + 8 * QP + 64];
            al[2] = qb[ro + 68];     al[3] = qb[ro + 8 * QP + 68];
            #pragma unroll
            for (int nt = 0; nt < 8; nt++) {
                const int rb = (nt * 8 + g) * QP + ks * 8 + t4;
                uint32_t bh[2] = { k_s[rb],      k_s[rb + 4]  };
                uint32_t bl[2] = { k_s[rb + 64], k_s[rb + 68] };
                mma_bf16(s[nt], ah, bh);
                mma_bf16(s[nt], ah, bl);
                mma_bf16(s[nt], al, bh);
            }
        }

        if (kt == bq) {
            #pragma unroll
            for (int nt = 0; nt < 8; nt++) {
                const int col = kt * 64 + nt * 8 + 2 * t4;
                if (col     > row0) s[nt][0] = -1e30f;
                if (col + 1 > row0) s[nt][1] = -1e30f;
                if (col     > row1) s[nt][2] = -1e30f;
                if (col + 1 > row1) s[nt][3] = -1e30f;
            }
        }

        float mt0 = -1e30f, mt1 = -1e30f;
        #pragma unroll
        for (int nt = 0; nt < 8; nt++) {
            mt0 = fmaxf(mt0, fmaxf(s[nt][0], s[nt][1]));
            mt1 = fmaxf(mt1, fmaxf(s[nt][2], s[nt][3]));
        }
        mt0 = fmaxf(mt0, __shfl_xor_sync(0xffffffffu, mt0, 1));
        mt0 = fmaxf(mt0, __shfl_xor_sync(0xffffffffu, mt0, 2));
        mt1 = fmaxf(mt1, __shfl_xor_sync(0xffffffffu, mt1, 1));
        mt1 = fmaxf(mt1, __shfl_xor_sync(0xffffffffu, mt1, 2));

        const float mn0 = fmaxf(m0, mt0), mn1 = fmaxf(m1, mt1);
        const float al0 = __expf(m0 - mn0), al1 = __expf(m1 - mn1);

        float ps0 = 0.0f, ps1 = 0.0f;
        #pragma unroll
        for (int nt = 0; nt < 8; nt++) {
            s[nt][0] = __expf(s[nt][0] - mn0);
            s[nt][1] = __expf(s[nt][1] - mn0);
            s[nt][2] = __expf(s[nt][2] - mn1);
            s[nt][3] = __expf(s[nt][3] - mn1);
            ps0 += s[nt][0] + s[nt][1];
            ps1 += s[nt][2] + s[nt][3];
        }
        ps0 += __shfl_xor_sync(0xffffffffu, ps0, 1);
        ps0 += __shfl_xor_sync(0xffffffffu, ps0, 2);
        ps1 += __shfl_xor_sync(0xffffffffu, ps1, 1);
        ps1 += __shfl_xor_sync(0xffffffffu, ps1, 2);
        l0 = l0 * al0 + ps0; m0 = mn0;
        l1 = l1 * al1 + ps1; m1 = mn1;

        #pragma unroll
        for (int nt = 0; nt < 16; nt++) {
            o[nt][0] *= al0; o[nt][1] *= al0;
            o[nt][2] *= al1; o[nt][3] *= al1;
        }

        #pragma unroll
        for (int jj = 0; jj < 4; jj++) {
            uint32_t ph[4], pl[4];
            pack_split2(s[2*jj][0],   s[2*jj][1],   ph[0], pl[0]);
            pack_split2(s[2*jj][2],   s[2*jj][3],   ph[1], pl[1]);
            pack_split2(s[2*jj+1][0], s[2*jj+1][1], ph[2], pl[2]);
            pack_split2(s[2*jj+1][2], s[2*jj+1][3], ph[3], pl[3]);

            const uint32_t rowaddr = v_base + (uint32_t)(((jj * 16 + (lid & 15)) * QP) * 4);
            #pragma unroll
            for (int nt = 0; nt < 16; nt++) {
                uint32_t bh[2], bl[2];
                ldsm_x2_t(bh[0], bh[1], rowaddr + nt * 16);
                ldsm_x2_t(bl[0], bl[1], rowaddr + 256 + nt * 16);
                mma_bf16(o[nt], ph, bh);
                mma_bf16(o[nt], ph, bl);
                mma_bf16(o[nt], pl, bh);
            }
        }
    }

    // epilogue: write fp16 directly (same _rn conversion the standalone pass did)
    const float i0 = 1.0f / l0, i1 = 1.0f / l1;
    #pragma unroll
    for (int nt = 0; nt < 16; nt++) {
        const int d = nt * 8 + 2 * t4;
        __half2 a = __floats2half2_rn(o[nt][0] * i0, o[nt][1] * i0);
        __half2 b = __floats2half2_rn(o[nt][2] * i1, o[nt][3] * i1);
        *(__half2*)&attn_h[(long)row0 * HID + h * HD + d] = a;
        *(__half2*)&attn_h[(long)row1 * HID + h * HD + d] = b;
    }
}

// ---------------------------------------------------------------------------
extern "C" void kernel_launch(void* const* d_in, const int* in_sizes, int n_in,
                              void* d_out, int out_size)
{
    const float* x    = (const float*)d_in[0];
    const float* wqkv = (const float*)d_in[1];
    const float* bqkv = (const float*)d_in[2];
    const float* wo   = (const float*)d_in[3];
    const float* bo   = (const float*)d_in[4];
    float* out = (float*)d_out;

    float  *qkv_buf;
    __half *wh, *woh, *ah;
    cudaGetSymbolAddress((void**)&qkv_buf, g_qkv);
    cudaGetSymbolAddress((void**)&wh,  g_wh);
    cudaGetSymbolAddress((void**)&woh, g_woh);
    cudaGetSymbolAddress((void**)&ah,  g_ah);

    const int gemm_smem = 4 * STG_B;                       // 81920
    cudaFuncSetAttribute(gemm_f16a,
                         cudaFuncAttributeMaxDynamicSharedMemorySize, gemm_smem);
    const int attn_smem = 3 * 64 * QP * sizeof(uint32_t);  // 101376
    cudaFuncSetAttribute(mqa_flash_hmma,
                         cudaFuncAttributeMaxDynamicSharedMemorySize, attn_smem);

    // 0) conversions (weights + input activations)
    {
        int n4 = (QKV_OUT * HID) / 4;
        f32_to_f16_k<<<(n4 + 255) / 256, 256>>>(wqkv, wh, n4);
        n4 = (HID * HID) / 4;
        f32_to_f16_k<<<(n4 + 255) / 256, 256>>>(wo, woh, n4);
        n4 = (S_LEN * HID) / 4;
        f32_to_f16_k<<<(n4 + 255) / 256, 256>>>(x, ah, n4);
    }

    // 1) QKV projection
    {
        dim3 grid(QKV_OUT / 128, S_LEN / 128);
        gemm_f16a<<<grid, 256, gemm_smem>>>(ah, wh, bqkv, qkv_buf, QKV_OUT);
    }
    // 2) attention (writes fp16 into g_ah, overwritten region only after use:
    //    g_ah input-x copy is fully consumed by GEMM1 before this launch)
    {
        dim3 grid(S_LEN / 64, NH);
        mqa_flash_hmma<<<grid, 128, attn_smem>>>(qkv_buf, ah);
    }
    // 3) output projection
    {
        dim3 grid(HID / 128, S_LEN / 128);
        gemm_f16a<<<grid, 256, gemm_smem>>>(ah, woh, bo, out, HID);
    }
}

// round 16
// speedup vs baseline: 1.2890x; 1.0654x over previous
#include <cuda_runtime.h>
#include <cuda_bf16.h>
#include <cuda_fp16.h>
#include <cstdint>

// Problem constants (B=1 fixed)
#define S_LEN   2048
#define HID     6144
#define QKV_OUT 6400   // HID + 2*128
#define NH      48
#define HD      128
#define KDIM    6144   // GEMM K (both projections)

// Scratch (no cudaMalloc allowed)
__device__ float  g_qkv [S_LEN * QKV_OUT];
__device__ __half g_wh  [QKV_OUT * HID];   // wqkv fp16
__device__ __half g_woh [HID * HID];       // wo fp16
__device__ __half g_ah  [S_LEN * HID];     // activation fp16 (GEMM A operand)

// ---------------------------------------------------------------------------
// helpers
// ---------------------------------------------------------------------------
__device__ __forceinline__ uint32_t smem_u32(const void* p) {
    uint32_t a;
    asm("{ .reg .u64 t; cvta.to.shared.u64 t, %1; cvt.u32.u64 %0, t; }"
        : "=r"(a) : "l"(p));
    return a;
}

__device__ __forceinline__ void cp16(uint32_t dst, const void* src) {
    asm volatile("cp.async.cg.shared.global [%0], [%1], 16;"
                 :: "r"(dst), "l"(src) : "memory");
}
#define CP_COMMIT() asm volatile("cp.async.commit_group;" ::: "memory")
#define CP_WAIT2()  asm volatile("cp.async.wait_group 2;" ::: "memory")

__device__ __forceinline__ void mma_bf16(float* d, const uint32_t* a, const uint32_t* b) {
    asm volatile(
        "mma.sync.aligned.m16n8k16.row.col.f32.bf16.bf16.f32 "
        "{%0,%1,%2,%3}, {%4,%5,%6,%7}, {%8,%9}, {%0,%1,%2,%3};"
        : "+f"(d[0]), "+f"(d[1]), "+f"(d[2]), "+f"(d[3])
        : "r"(a[0]), "r"(a[1]), "r"(a[2]), "r"(a[3]), "r"(b[0]), "r"(b[1]));
}
__device__ __forceinline__ void mma_f16(float* d, const uint32_t* a, const uint32_t* b) {
    asm volatile(
        "mma.sync.aligned.m16n8k16.row.col.f32.f16.f16.f32 "
        "{%0,%1,%2,%3}, {%4,%5,%6,%7}, {%8,%9}, {%0,%1,%2,%3};"
        : "+f"(d[0]), "+f"(d[1]), "+f"(d[2]), "+f"(d[3])
        : "r"(a[0]), "r"(a[1]), "r"(a[2]), "r"(a[3]), "r"(b[0]), "r"(b[1]));
}

__device__ __forceinline__ void ldsm_x4(uint32_t* r, uint32_t addr) {
    asm volatile("ldmatrix.sync.aligned.m8n8.x4.shared.b16 {%0,%1,%2,%3}, [%4];"
                 : "=r"(r[0]), "=r"(r[1]), "=r"(r[2]), "=r"(r[3]) : "r"(addr));
}
__device__ __forceinline__ void ldsm_x2(uint32_t* r, uint32_t addr) {
    asm volatile("ldmatrix.sync.aligned.m8n8.x2.shared.b16 {%0,%1}, [%2];"
                 : "=r"(r[0]), "=r"(r[1]) : "r"(addr));
}
__device__ __forceinline__ void ldsm_x2_t(uint32_t& r0, uint32_t& r1, uint32_t addr) {
    asm volatile("ldmatrix.sync.aligned.m8n8.x2.trans.shared.b16 {%0,%1}, [%2];"
                 : "=r"(r0), "=r"(r1) : "r"(addr));
}

// ---- bf16 split helpers (attention) ----
__device__ __forceinline__ void pack_split2(float x, float y, uint32_t& hi, uint32_t& lo) {
    __nv_bfloat162 h = __floats2bfloat162_rn(x, y);
    float2 hf = __bfloat1622float2(h);
    __nv_bfloat162 l = __floats2bfloat162_rn(x - hf.x, y - hf.y);
    hi = *reinterpret_cast<uint32_t*>(&h);
    lo = *reinterpret_cast<uint32_t*>(&l);
}
__device__ __forceinline__ void split16(const float* src, uint32_t* hi, uint32_t* lo,
                                        float scale) {
    #pragma unroll
    for (int i = 0; i < 4; i++) {
        float4 f = *(const float4*)(src + i * 4);
        f.x *= scale; f.y *= scale; f.z *= scale; f.w *= scale;
        uint32_t h0, l0, h1, l1;
        pack_split2(f.x, f.y, h0, l0);
        pack_split2(f.z, f.w, h1, l1);
        hi[i * 2] = h0; hi[i * 2 + 1] = h1;
        lo[i * 2] = l0; lo[i * 2 + 1] = l1;
    }
}

// ---------------------------------------------------------------------------
// conversion kernel (weights + input activations)
// ---------------------------------------------------------------------------
__global__ void __launch_bounds__(256) f32_to_f16_k(const float* __restrict__ in,
                                                    __half* __restrict__ out, int n4) {
    const int i = blockIdx.x * 256 + threadIdx.x;
    if (i < n4) {
        float4 f = ((const float4*)in)[i];
        __half2 a = __floats2half2_rn(f.x, f.y);
        __half2 b = __floats2half2_rn(f.z, f.w);
        ((uint2*)out)[i] = make_uint2(*reinterpret_cast<uint32_t*>(&a),
                                      *reinterpret_cast<uint32_t*>(&b));
    }
}

// ---------------------------------------------------------------------------
// fp16 async GEMM (R12 version — measured 565us). CTA 128x128, BK=32,
// 256 threads, warp tile 64x32, 4-stage cp.async ring, pitch 80B, 2 CTA/SM.
// ---------------------------------------------------------------------------
#define TILE_B 10240
#define STG_B  (2 * TILE_B)
#define NSTG   (KDIM / 32)

__global__ void __launch_bounds__(256, 2) gemm_f16a(
    const __half* __restrict__ Ah, const __half* __restrict__ Bh,
    const float* __restrict__ bias, float* __restrict__ C, int N)
{
    extern __shared__ char gsm[];
    const uint32_t smb = smem_u32(gsm);

    const int tid = threadIdx.x;
    const int wid = tid >> 5, lid = tid & 31;
    const int g   = lid >> 2;
    const int t4  = lid & 3;
    const int wr  = wid >> 2;
    const int wc  = wid & 3;

    const int bm = blockIdx.y * 128, bn = blockIdx.x * 128;

    const int lrow = tid >> 1;
    const int lel  = (tid & 1) * 16;
    const __half* Ag = Ah + (long)(bm + lrow) * KDIM + lel;
    const __half* Bg = Bh + (long)(bn + lrow) * KDIM + lel;
    const uint32_t sdst = smb + (uint32_t)(lrow * 80 + lel * 2);

    const uint32_t a_row = (uint32_t)((wr * 64 + (lid & 15)) * 80 + (lid >> 4) * 16);
    const uint32_t b_row = (uint32_t)((wc * 32 + (lid & 7)) * 80 + ((lid >> 3) & 1) * 16);

    float acc[4][4][4];
    #pragma unroll
    for (int i = 0; i < 4; i++)
        #pragma unroll
        for (int j = 0; j < 4; j++)
            #pragma unroll
            for (int k = 0; k < 4; k++) acc[i][j][k] = 0.0f;

    #pragma unroll
    for (int s = 0; s < 3; s++) {
        const uint32_t sb = sdst + s * STG_B;
        const long go = (long)s * 32;
        cp16(sb,          Ag + go);  cp16(sb + 16,          Ag + go + 8);
        cp16(sb + TILE_B, Bg + go);  cp16(sb + TILE_B + 16, Bg + go + 8);
        CP_COMMIT();
    }

    int slot = 0;
    for (int s = 0; s < NSTG; s++) {
        CP_WAIT2();
        __syncthreads();

        if (s + 3 < NSTG) {
            const int wslot = (slot + 3) & 3;
            const uint32_t sb = sdst + wslot * STG_B;
            const long go = (long)(s + 3) * 32;
            cp16(sb,          Ag + go);  cp16(sb + 16,          Ag + go + 8);
            cp16(sb + TILE_B, Bg + go);  cp16(sb + TILE_B + 16, Bg + go + 8);
        }
        CP_COMMIT();

        const uint32_t abase = smb + slot * STG_B + a_row;
        const uint32_t bbase = smb + slot * STG_B + TILE_B + b_row;

        #pragma unroll
        for (int ks = 0; ks < 2; ks++) {
            uint32_t ah[4][4];
            #pragma unroll
            for (int mt = 0; mt < 4; mt++)
                ldsm_x4(ah[mt], abase + ks * 32 + mt * (16 * 80));
            #pragma unroll
            for (int nt = 0; nt < 4; nt++) {
                uint32_t bh[2];
                ldsm_x2(bh, bbase + ks * 32 + nt * (8 * 80));
                #pragma unroll
                for (int mt = 0; mt < 4; mt++) mma_f16(acc[mt][nt], ah[mt], bh);
            }
        }

        slot = (slot + 1) & 3;
    }

    #pragma unroll
    for (int mt = 0; mt < 4; mt++) {
        const int row = bm + wr * 64 + mt * 16 + g;
        #pragma unroll
        for (int nt = 0; nt < 4; nt++) {
            const int col = bn + wc * 32 + nt * 8 + t4 * 2;
            const float b0 = bias[col], b1 = bias[col + 1];
            float2 lo, hi;
            lo.x = acc[mt][nt][0] + b0; lo.y = acc[mt][nt][1] + b1;
            hi.x = acc[mt][nt][2] + b0; hi.y = acc[mt][nt][3] + b1;
            *(float2*)&C[(long)row * N + col]       = lo;
            *(float2*)&C[(long)(row + 8) * N + col] = hi;
        }
    }
}

// ---------------------------------------------------------------------------
// MQA causal flash attention, bf16-split HMMA.
// 2 heads per CTA: 256 threads (8 warps); warps 0-3 -> head h0, 4-7 -> h1.
// Per-warp loop byte-identical to the proven R11 version. K/V tile loaded and
// split ONCE per CTA (256 threads, 2 chunks each) and shared by both heads.
// Epilogue writes fp16 into g_ah. BQ=64, BKV=64, D=128.
// ---------------------------------------------------------------------------
#define QP 132
#define ATILE (64 * QP)

__global__ void __launch_bounds__(256) mqa_flash_hmma(
    const float* __restrict__ qkv, __half* __restrict__ attn_h)
{
    extern __shared__ uint32_t asm_[];
    uint32_t* q_s = asm_;                 // 2 x [64][QP]
    uint32_t* k_s = q_s + 2 * ATILE;      // [64][QP]
    uint32_t* v_s = k_s + ATILE;          // [64][QP]

    const int h0 = blockIdx.y * 2;
    const int bq = blockIdx.x;
    const int q0 = bq * 64;
    const int tid = threadIdx.x;
    const int wid = tid >> 5, lid = tid & 31;
    const int g = lid >> 2, t4 = lid & 3;
    const int whead = wid >> 2;           // 0 or 1: head index within CTA
    const int w4    = wid & 3;            // warp within head

    const uint32_t v_base = smem_u32(v_s);

    // Q loader: 256 threads cover 2 head tiles; per tile 2 thr/row x 4 chunks.
    {
        const int qh  = tid >> 7;             // head
        const int lr  = (tid & 127) >> 1;     // row
        const int lc0 = (tid & 1) * 16;
        const float* src = qkv + (long)(q0 + lr) * QKV_OUT + (h0 + qh) * HD;
        uint32_t* dst = q_s + qh * ATILE + lr * QP;
        #pragma unroll
        for (int jj = 0; jj < 4; jj++) {
            const int c16 = lc0 + 32 * jj;
            split16(src + c16, dst + (c16 >> 1), dst + (c16 >> 1) + 64,
                    0.08838834764831845f);
        }
    }

    // K/V loader mapping: 4 threads per row, 2 chunks of 16 floats each.
    const int klr  = tid >> 2;
    const int klc0 = (tid & 3) * 16;

    float o[16][4];
    #pragma unroll
    for (int i = 0; i < 16; i++)
        #pragma unroll
        for (int j = 0; j < 4; j++) o[i][j] = 0.0f;
    float m0 = -1e30f, m1 = -1e30f, l0 = 0.0f, l1 = 0.0f;

    const int row0 = q0 + w4 * 16 + g;
    const int row1 = row0 + 8;

    for (int kt = 0; kt <= bq; kt++) {
        __syncthreads();
        {
            const float* kp = qkv + (long)(kt * 64 + klr) * QKV_OUT + HID;
            uint32_t* kd = k_s + klr * QP;
            uint32_t* vd = v_s + klr * QP;
            #pragma unroll
            for (int jj = 0; jj < 2; jj++) {
                const int c16 = klc0 + 64 * jj;
                split16(kp + c16,      kd + (c16 >> 1), kd + (c16 >> 1) + 64, 1.0f);
                split16(kp + HD + c16, vd + (c16 >> 1), vd + (c16 >> 1) + 64, 1.0f);
            }
        }
        __syncthreads();

        // ---- S = Q K^T (3-term bf16) ----
        float s[8][4];
        #pragma unroll
        for (int nt = 0; nt < 8; nt++)
            #pragma unroll
            for (int j = 0; j < 4; j++) s[nt][j] = 0.0f;

        const uint32_t* qb = q_s + whead * ATILE + (w4 * 16) * QP;
        #pragma unroll
        for (int ks = 0; ks < 8; ks++) {
            uint32_t ah[4], al[4];
            const int ro = g * QP + ks * 8 + t4;
            ah[0] = qb[ro];          ah[1] = qb[ro + 8 * QP];
            ah[2] = qb[ro + 4];      ah[3] = qb[ro + 8 * QP + 4];
            al[0] = qb[ro + 64];     al[1] = qb[ro + 8 * QP + 64];
            al[2] = qb[ro + 68];     al[3] = qb[ro + 8 * QP + 68];
            #pragma unroll
            for (int nt = 0; nt < 8; nt++) {
                const int rb = (nt * 8 + g) * QP + ks * 8 + t4;
                uint32_t bh[2] = { k_s[rb],      k_s[rb + 4]  };
                uint32_t bl[2] = { k_s[rb + 64], k_s[rb + 68] };
                mma_bf16(s[nt], ah, bh);
                mma_bf16(s[nt], ah, bl);
                mma_bf16(s[nt], al, bh);
            }
        }

        if (kt == bq) {
            #pragma unroll
            for (int nt = 0; nt < 8; nt++) {
                const int col = kt * 64 + nt * 8 + 2 * t4;
                if (col     > row0) s[nt][0] = -1e30f;
                if (col + 1 > row0) s[nt][1] = -1e30f;
                if (col     > row1) s[nt][2] = -1e30f;
                if (col + 1 > row1) s[nt][3] = -1e30f;
            }
        }

        float mt0 = -1e30f, mt1 = -1e30f;
        #pragma unroll
        for (int nt = 0; nt < 8; nt++) {
            mt0 = fmaxf(mt0, fmaxf(s[nt][0], s[nt][1]));
            mt1 = fmaxf(mt1, fmaxf(s[nt][2], s[nt][3]));
        }
        mt0 = fmaxf(mt0, __shfl_xor_sync(0xffffffffu, mt0, 1));
        mt0 = fmaxf(mt0, __shfl_xor_sync(0xffffffffu, mt0, 2));
        mt1 = fmaxf(mt1, __shfl_xor_sync(0xffffffffu, mt1, 1));
        mt1 = fmaxf(mt1, __shfl_xor_sync(0xffffffffu, mt1, 2));

        const float mn0 = fmaxf(m0, mt0), mn1 = fmaxf(m1, mt1);
        const float al0 = __expf(m0 - mn0), al1 = __expf(m1 - mn1);

        float ps0 = 0.0f, ps1 = 0.0f;
        #pragma unroll
        for (int nt = 0; nt < 8; nt++) {
            s[nt][0] = __expf(s[nt][0] - mn0);
            s[nt][1] = __expf(s[nt][1] - mn0);
            s[nt][2] = __expf(s[nt][2] - mn1);
            s[nt][3] = __expf(s[nt][3] - mn1);
            ps0 += s[nt][0] + s[nt][1];
            ps1 += s[nt][2] + s[nt][3];
        }
        ps0 += __shfl_xor_sync(0xffffffffu, ps0, 1);
        ps0 += __shfl_xor_sync(0xffffffffu, ps0, 2);
        ps1 += __shfl_xor_sync(0xffffffffu, ps1, 1);
        ps1 += __shfl_xor_sync(0xffffffffu, ps1, 2);
        l0 = l0 * al0 + ps0; m0 = mn0;
        l1 = l1 * al1 + ps1; m1 = mn1;

        #pragma unroll
        for (int nt = 0; nt < 16; nt++) {
            o[nt][0] *= al0; o[nt][1] *= al0;
            o[nt][2] *= al1; o[nt][3] *= al1;
        }

        // ---- O += P V (3-term bf16) ----
        #pragma unroll
        for (int jj = 0; jj < 4; jj++) {
            uint32_t ph[4], pl[4];
            pack_split2(s[2*jj][0],   s[2*jj][1],   ph[0], pl[0]);
            pack_split2(s[2*jj][2],   s[2*jj][3],   ph[1], pl[1]);
            pack_split2(s[2*jj+1][0], s[2*jj+1][1], ph[2], pl[2]);
            pack_split2(s[2*jj+1][2], s[2*jj+1][3], ph[3], pl[3]);

            const uint32_t rowaddr = v_base + (uint32_t)(((jj * 16 + (lid & 15)) * QP) * 4);
            #pragma unroll
            for (int nt = 0; nt < 16; nt++) {
                uint32_t bh[2], bl[2];
                ldsm_x2_t(bh[0], bh[1], rowaddr + nt * 16);
                ldsm_x2_t(bl[0], bl[1], rowaddr + 256 + nt * 16);
                mma_bf16(o[nt], ph, bh);
                mma_bf16(o[nt], ph, bl);
                mma_bf16(o[nt], pl, bh);
            }
        }
    }

    // epilogue: write fp16 directly into the GEMM3 A operand
    const float i0 = 1.0f / l0, i1 = 1.0f / l1;
    const int hh = h0 + whead;
    #pragma unroll
    for (int nt = 0; nt < 16; nt++) {
        const int d = nt * 8 + 2 * t4;
        __half2 a = __floats2half2_rn(o[nt][0] * i0, o[nt][1] * i0);
        __half2 b = __floats2half2_rn(o[nt][2] * i1, o[nt][3] * i1);
        *(__half2*)&attn_h[(long)row0 * HID + hh * HD + d] = a;
        *(__half2*)&attn_h[(long)row1 * HID + hh * HD + d] = b;
    }
}

// ---------------------------------------------------------------------------
extern "C" void kernel_launch(void* const* d_in, const int* in_sizes, int n_in,
                              void* d_out, int out_size)
{
    const float* x    = (const float*)d_in[0];
    const float* wqkv = (const float*)d_in[1];
    const float* bqkv = (const float*)d_in[2];
    const float* wo   = (const float*)d_in[3];
    const float* bo   = (const float*)d_in[4];
    float* out = (float*)d_out;

    float  *qkv_buf;
    __half *wh, *woh, *ah;
    cudaGetSymbolAddress((void**)&qkv_buf, g_qkv);
    cudaGetSymbolAddress((void**)&wh,  g_wh);
    cudaGetSymbolAddress((void**)&woh, g_woh);
    cudaGetSymbolAddress((void**)&ah,  g_ah);

    const int gemm_smem = 4 * STG_B;                       // 81920
    cudaFuncSetAttribute(gemm_f16a,
                         cudaFuncAttributeMaxDynamicSharedMemorySize, gemm_smem);
    const int attn_smem = 4 * ATILE * sizeof(uint32_t);    // 135168
    cudaFuncSetAttribute(mqa_flash_hmma,
                         cudaFuncAttributeMaxDynamicSharedMemorySize, attn_smem);

    // 0) conversions (weights + input activations)
    {
        int n4 = (QKV_OUT * HID) / 4;
        f32_to_f16_k<<<(n4 + 255) / 256, 256>>>(wqkv, wh, n4);
        n4 = (HID * HID) / 4;
        f32_to_f16_k<<<(n4 + 255) / 256, 256>>>(wo, woh, n4);
        n4 = (S_LEN * HID) / 4;
        f32_to_f16_k<<<(n4 + 255) / 256, 256>>>(x, ah, n4);
    }

    // 1) QKV projection
    {
        dim3 grid(QKV_OUT / 128, S_LEN / 128);
        gemm_f16a<<<grid, 256, gemm_smem>>>(ah, wh, bqkv, qkv_buf, QKV_OUT);
    }
    // 2) attention (2 heads per CTA; writes fp16 into g_ah)
    {
        dim3 grid(S_LEN / 64, NH / 2);
        mqa_flash_hmma<<<grid, 256, attn_smem>>>(qkv_buf, ah);
    }
    // 3) output projection
    {
        dim3 grid(HID / 128, S_LEN / 128);
        gemm_f16a<<<grid, 256, gemm_smem>>>(ah, woh, bo, out, HID);
    }
}